// round 15
// baseline (speedup 1.0000x reference)
#include <cuda_runtime.h>
#include <math.h>

// Problem constants
#define PB   128            // batch
#define PH   512            // hidden*2
#define PE   128            // embedding
#define PL   512            // encoder length
#define PV   50000          // vocab
#define POUTW (PV + PL)     // 50512
#define PG3  1536           // 3 * PH
#define NBLKV 391           // ceil(PV/128)

// ---------------------------------------------------------------------------
// Scratch (float offsets):
//  gx 0 (196608) | gh 196608 (196608) | comb 393216 (131072) | dsl 524288 (65536)
//  attn 589824 (65536) | o 655360 (16384) | pg 671744 (128) | vinv 671872 (128)
//  bsums 672000 (50048) | scores 722048 (65536)
// ---------------------------------------------------------------------------
__device__ __align__(16) float g_scratch[800000];

typedef unsigned long long ull;

__device__ __forceinline__ float wred_sum(float v) {
#pragma unroll
    for (int off = 16; off > 0; off >>= 1)
        v += __shfl_xor_sync(0xffffffffu, v, off);
    return v;
}
__device__ __forceinline__ float wred_max(float v) {
#pragma unroll
    for (int off = 16; off > 0; off >>= 1)
        v = fmaxf(v, __shfl_xor_sync(0xffffffffu, v, off));
    return v;
}
__device__ __forceinline__ float sigmoid_f(float x) {
    return __fdividef(1.f, 1.f + __expf(-x));
}
// exact tanh: tanh(x) = 1 - 2/(exp(2x)+1). Overflow/underflow give +/-1.
__device__ __forceinline__ float tanh_f(float x) {
    float t = __expf(2.f * x);
    return 1.f - __fdividef(2.f, t + 1.f);
}
__device__ __forceinline__ ull packdup(float a) {
    unsigned u = __float_as_uint(a);
    ull r;
    asm("mov.b64 %0, {%1, %1};" : "=l"(r) : "r"(u));
    return r;
}
__device__ __forceinline__ void fma2(ull& acc, ull a, ull b) {
    asm("fma.rn.f32x2 %0, %1, %2, %0;" : "+l"(acc) : "l"(a), "l"(b));
}
__device__ __forceinline__ void unpack2(ull p, float& lo, float& hi) {
    unsigned a, b;
    asm("mov.b64 {%0, %1}, %2;" : "=r"(a), "=r"(b) : "l"(p));
    lo = __uint_as_float(a); hi = __uint_as_float(b);
}

// ---------------------------------------------------------------------------
// Templated reduction GEMM, 2 batch rows per warp, fully unrolled k-loop.
// C[b][n0..n0+7] = bias + sum_k Arow_b[k]*W[n][k];  Arow = table[ids[b]] if ids.
// block = 8 warps sharing one n-group (W rows L1-resident); warp = (b, b+8).
// grid = (N/8) * 8.  Per-output sum order identical to the passing r12 kernel.
// ---------------------------------------------------------------------------
template<int K>
__global__ void __launch_bounds__(256) k_gemmT(
        const float* __restrict__ A, const int* __restrict__ ids, int lda,
        const float* __restrict__ W,
        const float* __restrict__ bias,
        float* __restrict__ C, int ldc) {
    int w = threadIdx.x >> 5, lane = threadIdx.x & 31;
    int n0 = (blockIdx.x >> 3) << 3;
    int btile = (blockIdx.x & 7) << 4;
    int b0 = btile + w;
    int b1 = btile + w + 8;
    const float* A0 = ids ? (A + (size_t)ids[b0] * lda) : (A + (size_t)b0 * lda);
    const float* A1 = ids ? (A + (size_t)ids[b1] * lda) : (A + (size_t)b1 * lda);
    float acc0[8] = {0.f, 0.f, 0.f, 0.f, 0.f, 0.f, 0.f, 0.f};
    float acc1[8] = {0.f, 0.f, 0.f, 0.f, 0.f, 0.f, 0.f, 0.f};
#pragma unroll
    for (int k0 = 0; k0 < K; k0 += 128) {
        int k = k0 + lane * 4;
        float4 a0 = *(const float4*)(A0 + k);
        float4 a1 = *(const float4*)(A1 + k);
#pragma unroll
        for (int j = 0; j < 8; j++) {
            float4 wv = *(const float4*)(W + (size_t)(n0 + j) * K + k);
            acc0[j] += a0.x * wv.x + a0.y * wv.y + a0.z * wv.z + a0.w * wv.w;
            acc1[j] += a1.x * wv.x + a1.y * wv.y + a1.z * wv.z + a1.w * wv.w;
        }
    }
#pragma unroll
    for (int j = 0; j < 8; j++) {
        acc0[j] = wred_sum(acc0[j]);
        acc1[j] = wred_sum(acc1[j]);
    }
    if (lane == 0) {
#pragma unroll
        for (int j = 0; j < 8; j++) {
            float bj = bias[n0 + j];
            C[(size_t)b0 * ldc + n0 + j] = acc0[j] + bj;
            C[(size_t)b1 * ldc + n0 + j] = acc1[j] + bj;
        }
    }
}

// ---------------------------------------------------------------------------
// GRU gates -> h_new, float4 vectorized. 64 blocks x 256 thr.
// ---------------------------------------------------------------------------
__global__ void __launch_bounds__(256) k_gates(
        const float* __restrict__ gx,
        const float* __restrict__ gh,
        const float* __restrict__ h0,
        float* __restrict__ comb,
        float* __restrict__ outH) {
    int idx = blockIdx.x * blockDim.x + threadIdx.x;   // 16384
    int b = idx >> 7, j4 = (idx & 127) * 4;            // b:0..127, j4:0..508
    int base = b * PG3 + j4;
    float4 xr = *(const float4*)(gx + base);
    float4 hr = *(const float4*)(gh + base);
    float4 xz = *(const float4*)(gx + base + 512);
    float4 hz = *(const float4*)(gh + base + 512);
    float4 xn = *(const float4*)(gx + base + 1024);
    float4 hn = *(const float4*)(gh + base + 1024);
    float4 h0v = *(const float4*)(h0 + b * PH + j4);
    float4 h;
    {
        float r = sigmoid_f(xr.x + hr.x), z = sigmoid_f(xz.x + hz.x);
        float n = tanh_f(xn.x + r * hn.x);
        h.x = (1.f - z) * n + z * h0v.x;
    }
    {
        float r = sigmoid_f(xr.y + hr.y), z = sigmoid_f(xz.y + hz.y);
        float n = tanh_f(xn.y + r * hn.y);
        h.y = (1.f - z) * n + z * h0v.y;
    }
    {
        float r = sigmoid_f(xr.z + hr.z), z = sigmoid_f(xz.z + hz.z);
        float n = tanh_f(xn.z + r * hn.z);
        h.z = (1.f - z) * n + z * h0v.z;
    }
    {
        float r = sigmoid_f(xr.w + hr.w), z = sigmoid_f(xz.w + hz.w);
        float n = tanh_f(xn.w + r * hn.w);
        h.w = (1.f - z) * n + z * h0v.w;
    }
    *(float4*)(comb + b * 1024 + j4) = h;
    *(float4*)(outH + b * PH + j4)   = h;
}

// ---------------------------------------------------------------------------
// attention scores. block = (b, 8 l's): dsl row staged ONCE in smem.
// grid 8192 x 256.
// ---------------------------------------------------------------------------
__global__ void __launch_bounds__(256) k_scores(
        const float* __restrict__ enc,
        const float* __restrict__ wh,
        const float* __restrict__ av,
        const float* __restrict__ dsl,
        float* __restrict__ scores) {
    __shared__ float ds[512];
    int b = blockIdx.x & 127;
    int ltile = blockIdx.x >> 7;   // 0..63
    int tid = threadIdx.x, lane = tid & 31, w = tid >> 5;
    if (tid < 128)
        *(float4*)&ds[tid * 4] = *(const float4*)(dsl + (size_t)b * PH + tid * 4);
    __syncthreads();
    int l = ltile * 8 + w;
    const float4* e4 = (const float4*)(enc + ((size_t)l * PB + b) * PH);
    float acc = 0.f;
#pragma unroll
    for (int i = 0; i < 4; i++) {
        int idx = lane + i * 32;
        float4 ev = e4[idx];
        float4 wv = *(const float4*)(wh + idx * 4);
        float4 avv = *(const float4*)(av + idx * 4);
        float4 dv = *(const float4*)&ds[idx * 4];
        acc += avv.x * tanh_f(wv.x * ev.x + dv.x);
        acc += avv.y * tanh_f(wv.y * ev.y + dv.y);
        acc += avv.z * tanh_f(wv.z * ev.z + dv.z);
        acc += avv.w * tanh_f(wv.w * ev.w + dv.w);
    }
    acc = wred_sum(acc);
    if (lane == 0) scores[l * PB + b] = acc;
}

// ---------------------------------------------------------------------------
// softmax over batch axis (dim=1) per l. 512 blocks x 128.
// ---------------------------------------------------------------------------
__global__ void __launch_bounds__(128) k_asoftmax(
        const float* __restrict__ scores,
        float* __restrict__ attn,
        float* __restrict__ outA) {
    int l = blockIdx.x;
    int t = threadIdx.x, lane = t & 31, w = t >> 5;
    __shared__ float sm[4], ss[4];
    float s = scores[l * PB + t];
    float m = wred_max(s);
    if (lane == 0) sm[w] = m;
    __syncthreads();
    m = fmaxf(fmaxf(sm[0], sm[1]), fmaxf(sm[2], sm[3]));
    float e = __expf(s - m);
    float su = wred_sum(e);
    if (lane == 0) ss[w] = su;
    __syncthreads();
    su = ss[0] + ss[1] + ss[2] + ss[3];
    float a = __fdividef(e, su);
    attn[l * PB + t] = a;
    outA[l * PB + t] = a;
}

// ---------------------------------------------------------------------------
// context[b][h] = sum_l attn[l][b]*enc[l][b][h]
// ---------------------------------------------------------------------------
__global__ void __launch_bounds__(256) k_context(
        const float* __restrict__ enc,
        const float* __restrict__ attn,
        float* __restrict__ comb) {
    int idx = blockIdx.x * blockDim.x + threadIdx.x;   // 65536
    int b = idx >> 9, h = idx & 511;
    const float* ep = enc + (size_t)b * PH + h;
    float a0 = 0.f, a1 = 0.f, a2 = 0.f, a3 = 0.f;
#pragma unroll 2
    for (int l = 0; l < PL; l += 8) {
        a0 += attn[(l    ) * PB + b] * ep[(size_t)(l    ) * PB * PH];
        a1 += attn[(l + 1) * PB + b] * ep[(size_t)(l + 1) * PB * PH];
        a2 += attn[(l + 2) * PB + b] * ep[(size_t)(l + 2) * PB * PH];
        a3 += attn[(l + 3) * PB + b] * ep[(size_t)(l + 3) * PB * PH];
        a0 += attn[(l + 4) * PB + b] * ep[(size_t)(l + 4) * PB * PH];
        a1 += attn[(l + 5) * PB + b] * ep[(size_t)(l + 5) * PB * PH];
        a2 += attn[(l + 6) * PB + b] * ep[(size_t)(l + 6) * PB * PH];
        a3 += attn[(l + 7) * PB + b] * ep[(size_t)(l + 7) * PB * PH];
    }
    comb[b * 1024 + 512 + h] = (a0 + a1) + (a2 + a3);
}

// ---------------------------------------------------------------------------
// Vocab GEMM + fused exp + per-block partial sums. f32x2, double buffered.
// ---------------------------------------------------------------------------
#define VLOADC(E0)                                                          \
    _Pragma("unroll")                                                       \
    for (int i = 0; i < 4; i++) {                                           \
        int lin = tid + i * 256;                                            \
        int row = lin >> 3, e4 = (lin & 7) * 4;                             \
        po[i] = *(const float4*)(o + row * 128 + (E0) + e4);                \
        int vg = v0 + row;                                                  \
        pw[i] = (vg < PV) ? *(const float4*)(Wov + (size_t)vg * 128 + (E0) + e4) \
                          : make_float4(0.f, 0.f, 0.f, 0.f);                \
    }

__global__ void __launch_bounds__(256) k_vocab_exp(
        const float* __restrict__ o,
        const float* __restrict__ Wov,
        const float* __restrict__ bov,
        float* __restrict__ out,
        float* __restrict__ bsums) {
    __shared__ float ot[32 * 132];   // [e][b]
    __shared__ float wt[32 * 132];   // [e][v]
    int tid = threadIdx.x, lane = tid & 31;
    int v0 = blockIdx.x * 128;
    int b0 = (tid >> 4) * 8;
    int vl = (tid & 15) * 8;
    ull acc[4][8];
#pragma unroll
    for (int i = 0; i < 4; i++)
#pragma unroll
        for (int j = 0; j < 8; j++) acc[i][j] = packdup(0.f);

    float4 po[4], pw[4];
    VLOADC(0)
    for (int e0 = 0; e0 < 128; e0 += 32) {
        __syncthreads();
#pragma unroll
        for (int i = 0; i < 4; i++) {
            int lin = tid + i * 256;
            int row = lin >> 3, e4 = (lin & 7) * 4;
            ot[(e4 + 0) * 132 + row] = po[i].x;
            ot[(e4 + 1) * 132 + row] = po[i].y;
            ot[(e4 + 2) * 132 + row] = po[i].z;
            ot[(e4 + 3) * 132 + row] = po[i].w;
            wt[(e4 + 0) * 132 + row] = pw[i].x;
            wt[(e4 + 1) * 132 + row] = pw[i].y;
            wt[(e4 + 2) * 132 + row] = pw[i].z;
            wt[(e4 + 3) * 132 + row] = pw[i].w;
        }
        __syncthreads();
        if (e0 + 32 < 128) { VLOADC(e0 + 32) }
#pragma unroll
        for (int ee = 0; ee < 32; ee++) {
            ulonglong2 X0 = *(const ulonglong2*)&ot[ee * 132 + b0];
            ulonglong2 X1 = *(const ulonglong2*)&ot[ee * 132 + b0 + 4];
            float4 w0 = *(const float4*)&wt[ee * 132 + vl];
            float4 w1 = *(const float4*)&wt[ee * 132 + vl + 4];
            float wf[8] = {w0.x, w0.y, w0.z, w0.w, w1.x, w1.y, w1.z, w1.w};
#pragma unroll
            for (int j = 0; j < 8; j++) {
                ull wd = packdup(wf[j]);
                fma2(acc[0][j], X0.x, wd);
                fma2(acc[1][j], X0.y, wd);
                fma2(acc[2][j], X1.x, wd);
                fma2(acc[3][j], X1.y, wd);
            }
        }
    }
    bool valid = (v0 + vl) < PV;
    float bias8[8];
#pragma unroll
    for (int j = 0; j < 8; j++) bias8[j] = valid ? bov[v0 + vl + j] : 0.f;
    float pb[8];
#pragma unroll
    for (int j = 0; j < 8; j++) pb[j] = 0.f;
#pragma unroll
    for (int bp = 0; bp < 4; bp++) {
        float vlo[8], vhi[8];
#pragma unroll
        for (int j = 0; j < 8; j++) {
            float flo, fhi;
            unpack2(acc[bp][j], flo, fhi);
            vlo[j] = valid ? __expf(flo + bias8[j]) : 0.f;
            vhi[j] = valid ? __expf(fhi + bias8[j]) : 0.f;
            pb[2 * bp]     += vlo[j];
            pb[2 * bp + 1] += vhi[j];
        }
        if (valid) {
            int blo = b0 + 2 * bp, bhi = blo + 1;
            float* plo = out + (size_t)blo * POUTW + v0 + vl;
            float* phi = out + (size_t)bhi * POUTW + v0 + vl;
            *(float4*)(plo)     = make_float4(vlo[0], vlo[1], vlo[2], vlo[3]);
            *(float4*)(plo + 4) = make_float4(vlo[4], vlo[5], vlo[6], vlo[7]);
            *(float4*)(phi)     = make_float4(vhi[0], vhi[1], vhi[2], vhi[3]);
            *(float4*)(phi + 4) = make_float4(vhi[4], vhi[5], vhi[6], vhi[7]);
        }
    }
#pragma unroll
    for (int off = 1; off < 16; off <<= 1)
#pragma unroll
        for (int j = 0; j < 8; j++)
            pb[j] += __shfl_xor_sync(0xffffffffu, pb[j], off);
    if ((lane & 15) == 0) {
#pragma unroll
        for (int j = 0; j < 8; j++)
            bsums[blockIdx.x * 128 + b0 + j] = pb[j];
    }
}

// ---------------------------------------------------------------------------
// merged: pg[b] = sigmoid(W_ptr.[comb|emb]+b_ptr); vinv[b] = pg[b]/sum(bsums).
// ---------------------------------------------------------------------------
__global__ void __launch_bounds__(128) k_vsum_pgen(
        const float* __restrict__ comb,
        const int* __restrict__ ids,
        const float* __restrict__ table,
        const float* __restrict__ Wp,
        const float* __restrict__ bp,
        const float* __restrict__ bsums,
        float* __restrict__ pg,
        float* __restrict__ vinv) {
    int b = blockIdx.x;
    int t = threadIdx.x, lane = t & 31, w = t >> 5;
    __shared__ float red[4], red2[4];
    const float* emb = table + (size_t)ids[b] * PE;
    float acc = 0.f;
    for (int k = t; k < 1152; k += 128) {
        float x = (k < 1024) ? comb[b * 1024 + k] : emb[k - 1024];
        acc += Wp[k] * x;
    }
    float s = 0.f;
    for (int i = t; i < NBLKV; i += 128) s += bsums[i * 128 + b];
    acc = wred_sum(acc);
    s   = wred_sum(s);
    if (lane == 0) { red[w] = acc; red2[w] = s; }
    __syncthreads();
    if (t == 0) {
        float d  = red[0] + red[1] + red[2] + red[3];
        float ss = red2[0] + red2[1] + red2[2] + red2[3];
        float p = sigmoid_f(d + bp[0]);
        pg[b] = p;
        vinv[b] = __fdividef(p, ss);
    }
}

// ---------------------------------------------------------------------------
// scale p_vocab rows by vinv[b]; zero pad. float4 grid.
// ---------------------------------------------------------------------------
__global__ void __launch_bounds__(256) k_vwrite(
        float* __restrict__ out,
        const float* __restrict__ vinv) {
    int b = blockIdx.y;
    int v4 = blockIdx.x * 256 + threadIdx.x;
    if (v4 >= POUTW / 4) return;
    float4* p = (float4*)(out + (size_t)b * POUTW) + v4;
    if (v4 < PV / 4) {
        float s = vinv[b];
        float4 x = *p;
        x.x *= s; x.y *= s; x.z *= s; x.w *= s;
        *p = x;
    } else {
        *p = make_float4(0.f, 0.f, 0.f, 0.f);
    }
}

// ---------------------------------------------------------------------------
// pointer/copy scatter: out[b][full_input[l][b]] += (1-pg[b])*attn[l][b]
// ---------------------------------------------------------------------------
__global__ void k_scatter(const int* __restrict__ full_input,
                          const float* __restrict__ attn,
                          const float* __restrict__ pg,
                          float* __restrict__ out) {
    int idx = blockIdx.x * blockDim.x + threadIdx.x;   // 65536 = l*128+b
    int b = idx & 127;
    float v = (1.f - pg[b]) * attn[idx];
    int tok = full_input[idx];
    atomicAdd(&out[(size_t)b * POUTW + tok], v);
}

// ---------------------------------------------------------------------------
// launch
// ---------------------------------------------------------------------------
extern "C" void kernel_launch(void* const* d_in, const int* in_sizes, int n_in,
                              void* d_out, int out_size) {
    const int*   ids    = (const int*)  d_in[0];
    const float* hidden = (const float*)d_in[1];
    const float* enc    = (const float*)d_in[2];
    const int*   finp   = (const int*)  d_in[3];
    const float* table  = (const float*)d_in[4];
    const float* W_ih   = (const float*)d_in[5];
    const float* W_hh   = (const float*)d_in[6];
    const float* b_ih   = (const float*)d_in[7];
    const float* b_hh   = (const float*)d_in[8];
    const float* W_ds   = (const float*)d_in[9];
    const float* b_ds   = (const float*)d_in[10];
    const float* w_h    = (const float*)d_in[11];
    const float* att_v  = (const float*)d_in[12];
    const float* W_oh   = (const float*)d_in[13];
    const float* b_oh   = (const float*)d_in[14];
    const float* W_ov   = (const float*)d_in[15];
    const float* b_ov   = (const float*)d_in[16];
    const float* W_ptr  = (const float*)d_in[17];
    const float* b_ptr  = (const float*)d_in[18];

    float* out  = (float*)d_out;
    float* outH = out + (size_t)PB * POUTW;
    float* outA = outH + (size_t)PB * PH;

    void* sp = nullptr;
    cudaGetSymbolAddress(&sp, g_scratch);
    float* S        = (float*)sp;
    float* S_gx     = S;
    float* S_gh     = S + 196608;
    float* S_comb   = S + 393216;
    float* S_dsl    = S + 524288;
    float* S_attn   = S + 589824;
    float* S_o      = S + 655360;
    float* S_pg     = S + 671744;
    float* S_vinv   = S + 671872;
    float* S_bsums  = S + 672000;
    float* S_scores = S + 722048;

    // 1) gx = emb @ W_ih^T (gather fused), K=128, 1536 blocks
    k_gemmT<128><<<(PG3 / 8) * 8, 256>>>(table, ids, PE, W_ih, b_ih, S_gx, PG3);
    // 2) gh = h0 @ W_hh^T, K=512, 1536 blocks
    k_gemmT<512><<<(PG3 / 8) * 8, 256>>>(hidden, nullptr, PH, W_hh, b_hh, S_gh, PG3);
    // 3) gates -> h_new
    k_gates<<<64, 256>>>(S_gx, S_gh, hidden, S_comb, outH);
    // 4) dsl = h_new @ W_ds^T, K=512, 512 blocks
    k_gemmT<512><<<(PH / 8) * 8, 256>>>(S_comb, nullptr, 1024, W_ds, b_ds, S_dsl, PH);
    // 5) attention scores (dsl staged per block)
    k_scores<<<8192, 256>>>(enc, w_h, att_v, S_dsl, S_scores);
    // 6) softmax over batch axis
    k_asoftmax<<<PL, 128>>>(S_scores, S_attn, outA);
    // 7) context -> combined[:, 512:]
    k_context<<<256, 256>>>(enc, S_attn, S_comb);
    // 8) o = combined @ W_oh^T, K=1024, 128 blocks
    k_gemmT<1024><<<(PE / 8) * 8, 256>>>(S_comb, nullptr, 1024, W_oh, b_oh, S_o, PE);
    // 9) vocab logits -> exp into d_out + per-block sums
    k_vocab_exp<<<NBLKV, 256>>>(S_o, W_ov, b_ov, out, S_bsums);
    // 10) pg + vinv (parallel, merged)
    k_vsum_pgen<<<PB, 128>>>(S_comb, ids, table, W_ptr, b_ptr, S_bsums, S_pg, S_vinv);
    // 11) scale + zero pad
    k_vwrite<<<dim3((POUTW / 4 + 255) / 256, PB), 256>>>(out, S_vinv);
    // 12) scatter copy distribution
    k_scatter<<<256, 256>>>(finp, S_attn, S_pg, out);
}